// round 3
// baseline (speedup 1.0000x reference)
#include <cuda_runtime.h>
#include <cstdint>

// result = (1/B) * sum [ (81 + cw(h)*cw(w))*x^2 - 2*x*box9(x) ],  box9 separable.
// Warp-independent column strips (shfl halo), vertical slide via L1 re-read,
// 4-deep register h-delay, no shared memory / no barriers in the hot loop.

#define HH 512
#define WW 512
#define STRIP 128
#define TILES (HH / STRIP)     // 4
#define NWARPS 5
#define TPB (NWARPS * 32)      // 160
#define NBLK 1024

__device__ double g_partials[NBLK];
__device__ unsigned int g_count = 0;

__device__ __forceinline__ float cw_h(int r) {
    float w = 9.f;
    if (r < 4) w = (float)(5 + r);
    if (r > HH - 5) w = (float)(HH + 4 - r);
    return w;
}

__device__ __forceinline__ float4 ldrow(const float* __restrict__ Pc, int rr, bool vc) {
    float4 v = make_float4(0.f, 0.f, 0.f, 0.f);
    if (vc && rr >= 0 && rr < HH) v = *(const float4*)(Pc + (size_t)rr * WW);
    return v;
}

// One pipeline step for row t = tb + J.
// Computes h[t] from vsum (shfl halo), accumulates row t-4 (if DO_ACC) using
// the old-row load needed for the vsum slide, then slides vsum to row t+1.
#define STEP(J, DO_ACC) do {                                                   \
    float s  = (vsum.x + vsum.y) + (vsum.z + vsum.w);                          \
    float sL = __shfl_up_sync(0xffffffffu, s, 1);                              \
    float Lx = __shfl_up_sync(0xffffffffu, vsum.x, 1);                         \
    float Ly = __shfl_up_sync(0xffffffffu, vsum.y, 1);                         \
    float Lz = __shfl_up_sync(0xffffffffu, vsum.z, 1);                         \
    float Rx = __shfl_down_sync(0xffffffffu, vsum.x, 1);                       \
    float Ry = __shfl_down_sync(0xffffffffu, vsum.y, 1);                       \
    float Rz = __shfl_down_sync(0xffffffffu, vsum.z, 1);                       \
    float Rw = __shfl_down_sync(0xffffffffu, vsum.w, 1);                       \
    if (left_edge) { sL = 0.f; Lx = 0.f; Ly = 0.f; Lz = 0.f; }                 \
    float4 hnew;                                                               \
    hnew.x = sL + s + Rx;                                                      \
    hnew.y = hnew.x - Lx + Ry;                                                 \
    hnew.z = hnew.y - Ly + Rz;                                                 \
    hnew.w = hnew.z - Lz + Rw;                                                 \
    const int t = tb + (J);                                                    \
    float4 xo = ldrow(Pc, t - 4, vcol);                                        \
    float4 nv = ldrow(Pc, t + 5, vcol);                                        \
    if (DO_ACC && acc_on) {                                                    \
        float4 ho = hring[J];                                                  \
        float wr = cw_h(t - 4);                                                \
        float v0 = xo.x * xo.x, v1 = xo.y * xo.y;                              \
        float v2 = xo.z * xo.z, v3 = xo.w * xo.w;                              \
        float rs = (v0 + v1) + (v2 + v3);                                      \
        SA += rs;                                                              \
        SB = fmaf(wr, rs, SB);                                                 \
        Bh = fmaf(xo.x, ho.x, Bh); Bh = fmaf(xo.y, ho.y, Bh);                  \
        Bh = fmaf(xo.z, ho.z, Bh); Bh = fmaf(xo.w, ho.w, Bh);                  \
        if (has_dwc) {                                                         \
            float e = fmaf(dwc.x, v0, fmaf(dwc.y, v1,                          \
                      fmaf(dwc.z, v2, dwc.w * v3)));                           \
            SE = fmaf(wr, e, SE);                                              \
        }                                                                      \
    }                                                                          \
    hring[J] = hnew;                                                           \
    vsum.x += nv.x - xo.x; vsum.y += nv.y - xo.y;                              \
    vsum.z += nv.z - xo.z; vsum.w += nv.w - xo.w;                              \
} while (0)

__global__ __launch_bounds__(TPB, 6) void scc_main_kernel(const float* __restrict__ img,
                                                          float* __restrict__ out,
                                                          double inv_b) {
    const int bid   = blockIdx.x;
    const int plane = bid / TILES;
    const int tile  = bid % TILES;
    const int r0    = tile * STRIP;
    const float* __restrict__ P = img + (size_t)plane * (HH * WW);

    const int tid  = threadIdx.x;
    const int w    = tid >> 5;
    const int lane = tid & 31;
    // warp w covers 128 cols starting at 120*w (8-col overlap with neighbor)
    const int c0 = 120 * w + 4 * lane;
    const bool vcol      = (c0 < WW);
    const bool left_edge = (c0 == 0);
    const bool acc_on    = (lane <= 30) && (lane >= 1 || w == 0) && vcol;
    const float* __restrict__ Pc = P + c0;

    // per-column cw deltas vs interior value 9 (nonzero only on 2 lanes of grid)
    float4 dwc;
    {
        float d[4];
        #pragma unroll
        for (int i = 0; i < 4; i++) {
            int c = c0 + i;
            int l = (c < 4) ? (4 - c) : 0;
            int rr = (c > WW - 5) ? (c - (WW - 5)) : 0;
            d[i] = (float)(-l - rr);
        }
        dwc = make_float4(d[0], d[1], d[2], d[3]);
    }
    const bool has_dwc = (dwc.x != 0.f) || (dwc.w != 0.f);

    // prefill vertical window sum for row r0
    float4 vsum = make_float4(0.f, 0.f, 0.f, 0.f);
    #pragma unroll
    for (int i = -4; i <= 4; i++) {
        float4 v = ldrow(Pc, r0 + i, vcol);
        vsum.x += v.x; vsum.y += v.y; vsum.z += v.z; vsum.w += v.w;
    }

    float4 hring[4];
    float SA = 0.f, SB = 0.f, SE = 0.f, Bh = 0.f;

    // prologue: rows r0..r0+3 (fill h ring; their t-4 rows belong to prev strip)
    {
        const int tb = r0;
        STEP(0, 0); STEP(1, 0); STEP(2, 0); STEP(3, 0);
    }
    // main: rows r0+4 .. r0+127 (accumulate rows r0 .. r0+123)
    for (int tb = r0 + 4; tb < r0 + STRIP; tb += 4) {
        STEP(0, 1); STEP(1, 1); STEP(2, 1); STEP(3, 1);
    }
    // epilogue: accumulate rows r0+124 .. r0+127
    if (acc_on) {
        #pragma unroll
        for (int J = 0; J < 4; J++) {
            const int t  = r0 + STRIP + J;
            float4 xo = ldrow(Pc, t - 4, vcol);
            float4 ho = hring[J];
            float wr = cw_h(t - 4);
            float v0 = xo.x * xo.x, v1 = xo.y * xo.y;
            float v2 = xo.z * xo.z, v3 = xo.w * xo.w;
            float rs = (v0 + v1) + (v2 + v3);
            SA += rs;
            SB = fmaf(wr, rs, SB);
            Bh = fmaf(xo.x, ho.x, Bh); Bh = fmaf(xo.y, ho.y, Bh);
            Bh = fmaf(xo.z, ho.z, Bh); Bh = fmaf(xo.w, ho.w, Bh);
            if (has_dwc) {
                float e = fmaf(dwc.x, v0, fmaf(dwc.y, v1,
                          fmaf(dwc.z, v2, dwc.w * v3)));
                SE = fmaf(wr, e, SE);
            }
        }
    }

    // combine in double:  81*SA + 9*SB + SE - 2*Bh
    double d = 81.0 * (double)SA + 9.0 * (double)SB + (double)SE - 2.0 * (double)Bh;

    // block reduction (fixed order -> deterministic)
    __shared__ double sred[NWARPS];
    __shared__ int slast;
    #pragma unroll
    for (int off = 16; off > 0; off >>= 1)
        d += __shfl_down_sync(0xffffffffu, d, off);
    if (lane == 0) sred[w] = d;
    __syncthreads();
    if (tid == 0) {
        double b = 0.0;
        #pragma unroll
        for (int i = 0; i < NWARPS; i++) b += sred[i];
        g_partials[bid] = b;
        __threadfence();
        unsigned int old = atomicAdd(&g_count, 1u);
        slast = (old == gridDim.x - 1) ? 1 : 0;
    }
    __syncthreads();

    if (slast) {
        __threadfence();
        double t = 0.0;
        const int nb = gridDim.x;
        for (int i = tid; i < nb; i += TPB)
            t += g_partials[i];
        #pragma unroll
        for (int off = 16; off > 0; off >>= 1)
            t += __shfl_down_sync(0xffffffffu, t, off);
        if (lane == 0) sred[w] = t;
        __syncthreads();
        if (tid == 0) {
            double tot = 0.0;
            #pragma unroll
            for (int i = 0; i < NWARPS; i++) tot += sred[i];
            out[0] = (float)(tot * inv_b);
            g_count = 0;   // reset for next graph replay
        }
    }
}

extern "C" void kernel_launch(void* const* d_in, const int* in_sizes, int n_in,
                              void* d_out, int out_size) {
    const float* img = (const float*)d_in[0];
    float* out = (float*)d_out;

    int nplanes = in_sizes[0] / (HH * WW);   // B*C = 256
    int batch   = nplanes / 32;              // C = 32 -> B = 8
    int nblocks = nplanes * TILES;           // 1024

    scc_main_kernel<<<nblocks, TPB>>>(img, out, 1.0 / (double)batch);
}

// round 4
// speedup vs baseline: 2.2574x; 2.2574x over previous
#include <cuda_runtime.h>
#include <cstdint>

// result = (1/B) * sum [ (81 + cw(h)*cw(w))*x^2 - 2*x*box9(x) ], box9 separable.
//   = 81*SA + 9*SB + SE - 2*Bh,  SA=Σx², SB=Σ cw_h x², SE=Σ cw_h dwc x², Bh=Σ x·box
// Vertical running sum in one float4 register, slide via L1 re-read of row t-4;
// that same re-read feeds a 4-deep deferred accumulation (h kept in hring[4]).
// Horizontal 9-sum via shared halo exchange, 2 rows per barrier, 4 buffers.

#define HH 512
#define WW 512
#define KRAD 4
#define TPB 128
#define STRIP 128
#define TILES (HH / STRIP)   // 4
#define NBLK 1024

__device__ double g_partials[NBLK];
__device__ unsigned int g_count = 0;

__device__ __forceinline__ float cw_h(int r) {
    float w = 9.f;
    if (r < 4) w = (float)(5 + r);
    else if (r > HH - 5) w = (float)(HH + 4 - r);
    return w;
}

__device__ __forceinline__ float4 ldrow(const float* __restrict__ Pc, int rr) {
    float4 v = make_float4(0.f, 0.f, 0.f, 0.f);
    if (rr >= 0 && rr < HH) v = *(const float4*)(Pc + (size_t)rr * WW);
    return v;
}

// Publish vsum (rows t-4..t+4) for row t into buffer BUF, load the slide rows,
// advance vsum to row t+1. xo[J] (= x(t-4)) stays live for the deferred accum.
#define PUBSLIDE(J, BUF, t) do {                                               \
    *(float4*)&vsbuf[BUF][KRAD + c0] = vsum;                                   \
    xo[J] = ldrow(Pc, (t) - 4);                                                \
    float4 nv = ldrow(Pc, (t) + 5);                                            \
    vsum.x += nv.x - xo[J].x; vsum.y += nv.y - xo[J].y;                        \
    vsum.z += nv.z - xo[J].z; vsum.w += nv.w - xo[J].w;                        \
} while (0)

// After the barrier: build h(t) from shared halos; accumulate row t-4 using
// xo[J] and hring[J]; then store h(t) into hring[J].
#define ACCROW(J, BUF, t, DO_ACC) do {                                         \
    float4 L = *(const float4*)&vsbuf[BUF][c0];                                \
    float4 O = *(const float4*)&vsbuf[BUF][KRAD + c0];                         \
    float4 R = *(const float4*)&vsbuf[BUF][KRAD + c0 + 4];                     \
    float4 h;                                                                  \
    float vall = (O.x + O.y) + (O.z + O.w);                                    \
    h.x = ((L.x + L.y) + (L.z + L.w)) + vall + R.x;                            \
    h.y = h.x - L.x + R.y;                                                     \
    h.z = h.y - L.y + R.z;                                                     \
    h.w = h.z - L.z + R.w;                                                     \
    if (DO_ACC) {                                                              \
        float4 xv = xo[J]; float4 ho = hring[J];                               \
        float wr = cw_h((t) - 4);                                              \
        float v0 = xv.x * xv.x, v1 = xv.y * xv.y;                              \
        float v2 = xv.z * xv.z, v3 = xv.w * xv.w;                              \
        float rs = (v0 + v1) + (v2 + v3);                                      \
        SA += rs;                                                              \
        SB = fmaf(wr, rs, SB);                                                 \
        Bh = fmaf(xv.x, ho.x, Bh); Bh = fmaf(xv.y, ho.y, Bh);                  \
        Bh = fmaf(xv.z, ho.z, Bh); Bh = fmaf(xv.w, ho.w, Bh);                  \
        if (has_dwc) {                                                         \
            float e = fmaf(dwc.x, v0, fmaf(dwc.y, v1,                          \
                      fmaf(dwc.z, v2, dwc.w * v3)));                           \
            SE = fmaf(wr, e, SE);                                              \
        }                                                                      \
    }                                                                          \
    hring[J] = h;                                                              \
} while (0)

#define CHUNK(tb, DO_ACC) do {                                                 \
    PUBSLIDE(0, 0, (tb));     PUBSLIDE(1, 1, (tb) + 1);                        \
    __syncthreads();                                                           \
    ACCROW(0, 0, (tb), DO_ACC);     ACCROW(1, 1, (tb) + 1, DO_ACC);            \
    PUBSLIDE(2, 2, (tb) + 2); PUBSLIDE(3, 3, (tb) + 3);                        \
    __syncthreads();                                                           \
    ACCROW(2, 2, (tb) + 2, DO_ACC); ACCROW(3, 3, (tb) + 3, DO_ACC);            \
} while (0)

__global__ __launch_bounds__(TPB, 8) void scc_main_kernel(const float* __restrict__ img,
                                                          float* __restrict__ out,
                                                          double inv_b) {
    const int bid   = blockIdx.x;
    const int plane = bid / TILES;
    const int tile  = bid % TILES;
    const int r0    = tile * STRIP;
    const float* __restrict__ P = img + (size_t)plane * (HH * WW);

    const int tid  = threadIdx.x;
    const int c0   = tid * 4;
    const float* __restrict__ Pc = P + c0;

    __shared__ float vsbuf[4][WW + 2 * KRAD];
    __shared__ double sred[4];
    __shared__ int slast;

    // zero horizontal halos once (4 buffers x 8 cells)
    if (tid < 32) {
        int b = tid >> 3;
        int i = tid & 7;
        int idx = (i < KRAD) ? i : (WW + i);   // 0..3, 516..519
        vsbuf[b][idx] = 0.0f;
    }

    // per-column cw deltas vs interior 9 (nonzero only on threads 0 and 127)
    float4 dwc;
    {
        float d[4];
        #pragma unroll
        for (int i = 0; i < 4; i++) {
            int c = c0 + i;
            int l = (c < 4) ? (4 - c) : 0;
            int rr = (c > WW - 5) ? (c - (WW - 5)) : 0;
            d[i] = (float)(-l - rr);
        }
        dwc = make_float4(d[0], d[1], d[2], d[3]);
    }
    const bool has_dwc = (dwc.x != 0.f) || (dwc.w != 0.f);

    // prefill vertical sum for row r0 (rows r0-4 .. r0+4)
    float4 vsum = make_float4(0.f, 0.f, 0.f, 0.f);
    #pragma unroll
    for (int i = -KRAD; i <= KRAD; i++) {
        float4 v = ldrow(Pc, r0 + i);
        vsum.x += v.x; vsum.y += v.y; vsum.z += v.z; vsum.w += v.w;
    }

    float4 xo[4];
    float4 hring[4];
    float SA = 0.f, SB = 0.f, SE = 0.f, Bh = 0.f;

    // prologue: rows r0..r0+3 fill hring; their t-4 rows belong to prev strip
    CHUNK(r0, 0);

    // main: rows r0+4 .. r0+127, accumulating rows r0 .. r0+123
    #pragma unroll 1
    for (int tb = r0 + 4; tb < r0 + STRIP; tb += 4) {
        CHUNK(tb, 1);
    }

    // epilogue: accumulate rows r0+124 .. r0+127 (re-loads hit L1)
    #pragma unroll
    for (int J = 0; J < 4; J++) {
        const int t = r0 + STRIP + J;
        float4 xv = ldrow(Pc, t - 4);
        float4 ho = hring[J];
        float wr = cw_h(t - 4);
        float v0 = xv.x * xv.x, v1 = xv.y * xv.y;
        float v2 = xv.z * xv.z, v3 = xv.w * xv.w;
        float rs = (v0 + v1) + (v2 + v3);
        SA += rs;
        SB = fmaf(wr, rs, SB);
        Bh = fmaf(xv.x, ho.x, Bh); Bh = fmaf(xv.y, ho.y, Bh);
        Bh = fmaf(xv.z, ho.z, Bh); Bh = fmaf(xv.w, ho.w, Bh);
        if (has_dwc) {
            float e = fmaf(dwc.x, v0, fmaf(dwc.y, v1,
                      fmaf(dwc.z, v2, dwc.w * v3)));
            SE = fmaf(wr, e, SE);
        }
    }

    // combine in double:  81*SA + 9*SB + SE - 2*Bh
    double d = 81.0 * (double)SA + 9.0 * (double)SB
             + (double)SE - 2.0 * (double)Bh;

    // block reduction (fixed order -> deterministic)
    const int w    = tid >> 5;
    const int lane = tid & 31;
    #pragma unroll
    for (int off = 16; off > 0; off >>= 1)
        d += __shfl_down_sync(0xffffffffu, d, off);
    if (lane == 0) sred[w] = d;
    __syncthreads();
    if (tid == 0) {
        g_partials[bid] = (sred[0] + sred[1]) + (sred[2] + sred[3]);
        __threadfence();
        unsigned int old = atomicAdd(&g_count, 1u);
        slast = (old == gridDim.x - 1) ? 1 : 0;
    }
    __syncthreads();

    // last block reduces all partials (fixed order -> deterministic)
    if (slast) {
        __threadfence();
        double t = 0.0;
        const int nb = gridDim.x;
        for (int i = tid; i < nb; i += TPB)
            t += g_partials[i];
        #pragma unroll
        for (int off = 16; off > 0; off >>= 1)
            t += __shfl_down_sync(0xffffffffu, t, off);
        if (lane == 0) sred[w] = t;
        __syncthreads();
        if (tid == 0) {
            double tot = (sred[0] + sred[1]) + (sred[2] + sred[3]);
            out[0] = (float)(tot * inv_b);
            g_count = 0;   // reset for next graph replay
        }
    }
}

extern "C" void kernel_launch(void* const* d_in, const int* in_sizes, int n_in,
                              void* d_out, int out_size) {
    const float* img = (const float*)d_in[0];
    float* out = (float*)d_out;

    int nplanes = in_sizes[0] / (HH * WW);   // B*C = 256
    int batch   = nplanes / 32;              // C = 32 -> B = 8
    int nblocks = nplanes * TILES;           // 1024

    scc_main_kernel<<<nblocks, TPB>>>(img, out, 1.0 / (double)batch);
}